// round 4
// baseline (speedup 1.0000x reference)
#include <cuda_runtime.h>

#define N_NODES 1000000
#define DEGREE 31
#define BLOCK 256
#define THRESH 16
#define TILES ((N_NODES + BLOCK - 1) / BLOCK)   // 3907
#define GRID_PERSIST (148 * 6)                  // fully covers 6 CTA/SM residency

__device__ float  g_p[N_NODES];
__device__ double g_sum;
__device__ int    g_is64;
__device__ unsigned int g_done = 0;

// Kernel 1: p = sigmoid(gains). Block 0 warp 0 also detects index dtype and
// zeroes the accumulator.
__global__ void __launch_bounds__(BLOCK) prep_kernel(const float* __restrict__ gains,
                                                     const int* __restrict__ nb_raw) {
    int i = blockIdx.x * BLOCK + threadIdx.x;
    if (blockIdx.x == 0 && threadIdx.x < 32) {
        // If int64, hi-words of the first 32 elements are all 0 (indices < 2^20).
        // If int32, those words are random indices in [0, 1e6): P(all 0) ~ 0.
        int hi = nb_raw[threadIdx.x * 2 + 1];
        unsigned all0 = __ballot_sync(0xffffffffu, hi == 0);
        if (threadIdx.x == 0) {
            g_is64 = (all0 == 0xffffffffu) ? 1 : 0;
            g_sum = 0.0;
        }
    }
    if (i < N_NODES) {
        float x = gains[i];
        g_p[i] = 1.0f / (1.0f + __expf(-x));
    }
}

// Per-thread Poisson-binomial DP with absorbing state at THRESH.
__device__ __forceinline__ float dp_node(const float* __restrict__ pv) {
    float dp[THRESH + 1];
    dp[0] = 1.0f;
    #pragma unroll
    for (int k = 1; k <= THRESH; k++) dp[k] = 0.0f;

    #pragma unroll
    for (int j = 0; j < DEGREE + 1; j++) {
        const float pj = pv[j];
        const int kmax = (j + 1 < THRESH) ? (j + 1) : THRESH;  // triangular prune
        if (kmax == THRESH)
            dp[THRESH] = fmaf(pj, dp[THRESH - 1], dp[THRESH]); // absorbing state
        #pragma unroll
        for (int k = THRESH - 1; k >= 1; k--)
            if (k <= kmax)
                dp[k] = fmaf(pj, dp[k - 1] - dp[k], dp[k]);
        dp[0] = dp[0] * (1.0f - pj);
    }
    return dp[THRESH];
}

// Kernel 2 (persistent): grid-stride over node tiles. Stage indices coalesced
// into smem, gather p from the L2-resident table, run the DP, accumulate per
// thread. One atomic per block at the end; last block writes the output.
__global__ void __launch_bounds__(BLOCK, 6) dp_kernel(const void* __restrict__ neighbors,
                                                      float* __restrict__ out) {
    __shared__ int   sidx[BLOCK * DEGREE];
    __shared__ float sred[BLOCK / 32];

    const int tid = threadIdx.x;
    const int is64 = g_is64;
    float acc = 0.0f;

    for (int tile = blockIdx.x; tile < TILES; tile += gridDim.x) {
        const long long blockStart = (long long)tile * BLOCK;
        const int count = (int)min((long long)BLOCK, (long long)N_NODES - blockStart);
        const long long elemBase = blockStart * (long long)DEGREE;

        // Coalesced, vectorized staging of this tile's neighbor rows into smem.
        if (is64) {
            const int4* nb4 = (const int4*)((const long long*)neighbors + elemBase);
            if (count == BLOCK) {
                #pragma unroll 4
                for (int t = tid; t < BLOCK * DEGREE / 2; t += BLOCK) {
                    int4 v = nb4[t];
                    sidx[2 * t]     = v.x;
                    sidx[2 * t + 1] = v.z;
                }
            } else {
                for (int t = tid; t < count * DEGREE / 2; t += BLOCK) {
                    int4 v = nb4[t];
                    sidx[2 * t]     = v.x;
                    sidx[2 * t + 1] = v.z;
                }
            }
        } else {
            const int4* nb4 = (const int4*)((const int*)neighbors + elemBase);
            if (count == BLOCK) {
                #pragma unroll 4
                for (int t = tid; t < BLOCK * DEGREE / 4; t += BLOCK) {
                    int4 v = nb4[t];
                    sidx[4 * t]     = v.x;
                    sidx[4 * t + 1] = v.y;
                    sidx[4 * t + 2] = v.z;
                    sidx[4 * t + 3] = v.w;
                }
            } else {
                int tot = count * DEGREE;
                for (int t = tid; t < tot / 4; t += BLOCK) {
                    int4 v = nb4[t];
                    sidx[4 * t]     = v.x;
                    sidx[4 * t + 1] = v.y;
                    sidx[4 * t + 2] = v.z;
                    sidx[4 * t + 3] = v.w;
                }
                for (int t = (tot / 4) * 4 + tid; t < tot; t += BLOCK)
                    sidx[t] = ((const int*)neighbors)[elemBase + t];
            }
        }
        __syncthreads();

        if (tid < count) {
            const int node = (int)(blockStart + tid);
            float pv[DEGREE + 1];
            pv[0] = g_p[node];
            #pragma unroll
            for (int j = 0; j < DEGREE; j++) {
                int idx = sidx[tid * DEGREE + j];
                idx = min(max(idx, 0), N_NODES - 1);   // crash-proofing
                pv[j + 1] = __ldg(&g_p[idx]);
            }
            acc += dp_node(pv) - 0.25f * pv[0];
        }
        __syncthreads();   // sidx reuse guard for next tile
    }

    // Warp reduce -> block reduce -> one double atomic per block.
    #pragma unroll
    for (int o = 16; o; o >>= 1)
        acc += __shfl_down_sync(0xffffffffu, acc, o);
    if ((tid & 31) == 0) sred[tid >> 5] = acc;
    __syncthreads();
    if (tid < 32) {
        float v = (tid < BLOCK / 32) ? sred[tid] : 0.0f;
        #pragma unroll
        for (int o = 4; o; o >>= 1)
            v += __shfl_down_sync(0xffffffffu, v, o);
        if (tid == 0) {
            atomicAdd(&g_sum, (double)v);
            __threadfence();
            unsigned int done = atomicAdd(&g_done, 1u);
            if (done == (unsigned)gridDim.x - 1u) {
                double s = atomicAdd(&g_sum, 0.0);   // L2-coherent read
                out[0] = -(float)s;
                g_done = 0;                           // reset for graph replays
            }
        }
    }
}

extern "C" void kernel_launch(void* const* d_in, const int* in_sizes, int n_in,
                              void* d_out, int out_size) {
    // Resolve input order from element counts (gains: 1M, neighbors: 31M).
    int gi = 0, ni = 1;
    if (in_sizes[0] != N_NODES) { gi = 1; ni = 0; }
    const float* gains     = (const float*)d_in[gi];
    const void*  neighbors = d_in[ni];
    float*       out       = (float*)d_out;

    const int nblk_prep = (N_NODES + BLOCK - 1) / BLOCK;
    const int nblk_dp   = (TILES < GRID_PERSIST) ? TILES : GRID_PERSIST;
    prep_kernel<<<nblk_prep, BLOCK>>>(gains, (const int*)neighbors);
    dp_kernel<<<nblk_dp, BLOCK>>>(neighbors, out);
}

// round 5
// speedup vs baseline: 1.1306x; 1.1306x over previous
#include <cuda_runtime.h>

#define N_NODES 1000000
#define DEGREE 31
#define BLOCK 256
#define THRESH 16
#define TILES ((N_NODES + BLOCK - 1) / BLOCK)   // 3907

__device__ float  g_p[N_NODES];
__device__ double g_sum;
__device__ int    g_is64;
__device__ unsigned int g_done = 0;

// Kernel 1: p = sigmoid(gains). Block 0 warp 0 also detects index dtype and
// zeroes the accumulator.
__global__ void __launch_bounds__(BLOCK) prep_kernel(const float* __restrict__ gains,
                                                     const int* __restrict__ nb_raw) {
    int i = blockIdx.x * BLOCK + threadIdx.x;
    if (blockIdx.x == 0 && threadIdx.x < 32) {
        // If int64, hi-words of the first 32 elements are all 0 (indices < 2^20).
        // If int32, those words are random indices in [0, 1e6): P(all 0) ~ 0.
        int hi = nb_raw[threadIdx.x * 2 + 1];
        unsigned all0 = __ballot_sync(0xffffffffu, hi == 0);
        if (threadIdx.x == 0) {
            g_is64 = (all0 == 0xffffffffu) ? 1 : 0;
            g_sum = 0.0;
        }
    }
    if (i < N_NODES) {
        float x = gains[i];
        g_p[i] = 1.0f / (1.0f + __expf(-x));
    }
}

// Per-thread Poisson-binomial DP with absorbing state at THRESH.
__device__ __forceinline__ float dp_node(const float* __restrict__ pv) {
    float dp[THRESH + 1];
    dp[0] = 1.0f;
    #pragma unroll
    for (int k = 1; k <= THRESH; k++) dp[k] = 0.0f;

    #pragma unroll
    for (int j = 0; j < DEGREE + 1; j++) {
        const float pj = pv[j];
        const int kmax = (j + 1 < THRESH) ? (j + 1) : THRESH;  // triangular prune
        if (kmax == THRESH)
            dp[THRESH] = fmaf(pj, dp[THRESH - 1], dp[THRESH]); // absorbing state
        #pragma unroll
        for (int k = THRESH - 1; k >= 1; k--)
            if (k <= kmax)
                dp[k] = fmaf(pj, dp[k - 1] - dp[k], dp[k]);
        dp[0] = dp[0] * (1.0f - pj);
    }
    return dp[THRESH];
}

// Kernel 2: warp-autonomous. Each warp stages its own 32 rows of indices
// (coalesced int4), __syncwarp, gathers p from the L2-resident table, runs the
// DP. No block-wide barrier in the hot path. N_NODES % 32 == 0, so every warp
// is fully active or fully idle.
__global__ void __launch_bounds__(BLOCK) dp_kernel(const void* __restrict__ neighbors,
                                                   float* __restrict__ out) {
    __shared__ int   sidx[BLOCK * DEGREE];   // per-warp slices of 32*DEGREE
    __shared__ float sred[BLOCK / 32];

    const int tid  = threadIdx.x;
    const int wid  = tid >> 5;
    const int lane = tid & 31;
    const long long warpStart = (long long)blockIdx.x * BLOCK + wid * 32;

    float contrib = 0.0f;
    if (warpStart < N_NODES) {
        int* sw = sidx + wid * (32 * DEGREE);
        const long long elemBase = warpStart * (long long)DEGREE;

        // Stage this warp's 32x31 index rows, coalesced + vectorized.
        if (g_is64) {
            // 992 int64 = 496 int4 (low words at .x and .z).
            const int4* nb4 = (const int4*)((const long long*)neighbors + elemBase);
            #pragma unroll
            for (int t = lane; t < (32 * DEGREE) / 2; t += 32) {
                int4 v = nb4[t];
                sw[2 * t]     = v.x;
                sw[2 * t + 1] = v.z;
            }
        } else {
            // 992 int32 = 248 int4.
            const int4* nb4 = (const int4*)((const int*)neighbors + elemBase);
            #pragma unroll
            for (int t = lane; t < (32 * DEGREE) / 4; t += 32) {
                int4 v = nb4[t];
                sw[4 * t]     = v.x;
                sw[4 * t + 1] = v.y;
                sw[4 * t + 2] = v.z;
                sw[4 * t + 3] = v.w;
            }
        }
        __syncwarp();

        const int node = (int)(warpStart + lane);
        float pv[DEGREE + 1];
        pv[0] = g_p[node];
        #pragma unroll
        for (int j = 0; j < DEGREE; j++) {
            int idx = sw[lane * DEGREE + j];       // stride 31: bank-conflict-free
            idx = min(max(idx, 0), N_NODES - 1);   // crash-proofing
            pv[j + 1] = __ldg(&g_p[idx]);
        }
        contrib = dp_node(pv) - 0.25f * pv[0];
    }

    // Warp reduce -> block reduce -> one double atomic per block.
    #pragma unroll
    for (int o = 16; o; o >>= 1)
        contrib += __shfl_down_sync(0xffffffffu, contrib, o);
    if (lane == 0) sred[wid] = contrib;
    __syncthreads();
    if (tid < 32) {
        float v = (tid < BLOCK / 32) ? sred[tid] : 0.0f;
        #pragma unroll
        for (int o = 4; o; o >>= 1)
            v += __shfl_down_sync(0xffffffffu, v, o);
        if (tid == 0) {
            atomicAdd(&g_sum, (double)v);
            __threadfence();
            unsigned int done = atomicAdd(&g_done, 1u);
            if (done == (unsigned)gridDim.x - 1u) {
                double s = atomicAdd(&g_sum, 0.0);   // L2-coherent read
                out[0] = -(float)s;
                g_done = 0;                           // reset for graph replays
            }
        }
    }
}

extern "C" void kernel_launch(void* const* d_in, const int* in_sizes, int n_in,
                              void* d_out, int out_size) {
    // Resolve input order from element counts (gains: 1M, neighbors: 31M).
    int gi = 0, ni = 1;
    if (in_sizes[0] != N_NODES) { gi = 1; ni = 0; }
    const float* gains     = (const float*)d_in[gi];
    const void*  neighbors = d_in[ni];
    float*       out       = (float*)d_out;

    prep_kernel<<<TILES, BLOCK>>>(gains, (const int*)neighbors);
    dp_kernel<<<TILES, BLOCK>>>(neighbors, out);
}